// round 8
// baseline (speedup 1.0000x reference)
#include <cuda_runtime.h>
#include <cuda_bf16.h>
#include <math.h>
#include <stdint.h>

// ---------------------------------------------------------------------------
// Problem constants
// ---------------------------------------------------------------------------
#define TOK   5760          // 5*24*48
#define CH    256
#define DD    5
#define HH    24
#define WW    48
#define NHEAD 8
#define HDIM  32

// scratch buffers (static device globals; no dynamic allocation allowed)
__device__ float g_qkv [TOK * 768];
__device__ float g_attn[TOK * CH];
__device__ float g_x0  [TOK * CH];
__device__ float g_x1  [TOK * CH];
__device__ float g_feats[512 * TOK];                 // channel-first (512, 5, 24, 48)
__device__ float g_p0  [256 * 8 * 48 * 96];
__device__ float g_p1  [128 * 16 * 96 * 192];
__device__ float g_s0  [256 * 48 * 96];
__device__ float g_s1  [128 * 96 * 192];

// bf16 split scratch (hi/lo), canonical layouts A[M][K], B[N][K]
__device__ __align__(16) __nv_bfloat16 g_mah[1536 * 1024];   // A-side (max 5760*256)
__device__ __align__(16) __nv_bfloat16 g_mal[1536 * 1024];
__device__ __align__(16) __nv_bfloat16 g_mbh[36864 * 256];   // B-side (max p0T)
__device__ __align__(16) __nv_bfloat16 g_mbl[36864 * 256];

// ---------------------------------------------------------------------------
// fp32 -> bf16 hi/lo split, contiguous
// ---------------------------------------------------------------------------
__global__ void split_rows(const float* __restrict__ in,
                           __nv_bfloat16* __restrict__ oh,
                           __nv_bfloat16* __restrict__ ol, int n)
{
    int i = blockIdx.x * blockDim.x + threadIdx.x;
    if (i < n) {
        float v = in[i];
        __nv_bfloat16 h = __float2bfloat16(v);
        oh[i] = h;
        ol[i] = __float2bfloat16(v - __bfloat162float(h));
    }
}

// fp32 [R][C] (row stride ld) -> bf16 hi/lo [C][R]   (R, C multiples of 32)
__global__ void transpose_split(const float* __restrict__ in,
                                __nv_bfloat16* __restrict__ oh,
                                __nv_bfloat16* __restrict__ ol,
                                int R, int C, int ld)
{
    __shared__ float t[32][33];
    const int r0 = blockIdx.y * 32, c0 = blockIdx.x * 32;
    const int tx = threadIdx.x, ty = threadIdx.y;
    #pragma unroll
    for (int i = ty; i < 32; i += 8)
        t[i][tx] = in[(size_t)(r0 + i) * ld + c0 + tx];
    __syncthreads();
    #pragma unroll
    for (int i = ty; i < 32; i += 8) {
        float v = t[tx][i];
        __nv_bfloat16 h = __float2bfloat16(v);
        oh[(size_t)(c0 + i) * R + r0 + tx] = h;
        ol[(size_t)(c0 + i) * R + r0 + tx] = __float2bfloat16(v - __bfloat162float(h));
    }
}

// ---------------------------------------------------------------------------
// Tensor-core GEMM, bf16x3 split (hi*hi + hi*lo + lo*hi), fp32 accum.
//   C[m][n] = epilogue( sum_k A[m][k]*B[k][n] + bias )
// A given as Ah/Al [M][K] bf16, B as Bh/Bl [N][K] bf16.
// Tile 128x128x32, 256 threads = 8 warps (2 m x 4 n), warp tile 64x32,
// mma.sync.m16n8k16. M, N multiples of 128; K multiple of 32.
// MODE 0: C row-major [M][ldc], bias[n]
// MODE 1: C row-major [M][ldc], bias[m]
// MODE 2: up3d scatter, bias[m>>3], optional SiLU
// ---------------------------------------------------------------------------
#define MMA_BF16(c, a0, a1, a2, a3, b0, b1)                                   \
    asm volatile("mma.sync.aligned.m16n8k16.row.col.f32.bf16.bf16.f32 "       \
                 "{%0,%1,%2,%3}, {%4,%5,%6,%7}, {%8,%9}, {%0,%1,%2,%3};"      \
                 : "+f"(c[0]), "+f"(c[1]), "+f"(c[2]), "+f"(c[3])             \
                 : "r"(a0), "r"(a1), "r"(a2), "r"(a3), "r"(b0), "r"(b1))

template<int MODE, bool SILU>
__global__ __launch_bounds__(256)
void gemm_mma(const __nv_bfloat16* __restrict__ Ah, const __nv_bfloat16* __restrict__ Al,
              const __nv_bfloat16* __restrict__ Bh, const __nv_bfloat16* __restrict__ Bl,
              const float* __restrict__ bias, float* __restrict__ C,
              int M, int N, int K, int ldc, int Din, int Hin, int Win)
{
    constexpr int RS = 20;                         // smem words per row (16 data + 4 pad)
    __shared__ float sAh[128 * RS], sAl[128 * RS];
    __shared__ float sBh[128 * RS], sBl[128 * RS];

    const int tid  = threadIdx.x;
    const int warp = tid >> 5, lane = tid & 31;
    const int g = lane >> 2, t = lane & 3;
    const int wm = warp & 1, wn = warp >> 1;       // warp tile origin (wm*64, wn*32)
    const int m0 = blockIdx.y * 128, n0 = blockIdx.x * 128;

    const int lrow = tid >> 1, lseg = tid & 1;     // loader: 2 threads/row, 16 bf16 each

    float acc[4][4][4];
    #pragma unroll
    for (int a = 0; a < 4; a++)
        #pragma unroll
        for (int b = 0; b < 4; b++)
            #pragma unroll
            for (int c = 0; c < 4; c++) acc[a][b][c] = 0.f;

    const uint32_t* wAh = (const uint32_t*)sAh;
    const uint32_t* wAl = (const uint32_t*)sAl;
    const uint32_t* wBh = (const uint32_t*)sBh;
    const uint32_t* wBl = (const uint32_t*)sBl;

    for (int k0 = 0; k0 < K; k0 += 32) {
        {
            const size_t ga = (size_t)(m0 + lrow) * K + k0 + lseg * 16;
            const size_t gb = (size_t)(n0 + lrow) * K + k0 + lseg * 16;
            const uint4* pah = (const uint4*)(Ah + ga);
            const uint4* pal = (const uint4*)(Al + ga);
            const uint4* pbh = (const uint4*)(Bh + gb);
            const uint4* pbl = (const uint4*)(Bl + gb);
            uint4* dah = (uint4*)&sAh[lrow * RS + lseg * 8];
            uint4* dal = (uint4*)&sAl[lrow * RS + lseg * 8];
            uint4* dbh = (uint4*)&sBh[lrow * RS + lseg * 8];
            uint4* dbl = (uint4*)&sBl[lrow * RS + lseg * 8];
            dah[0] = pah[0]; dah[1] = pah[1];
            dal[0] = pal[0]; dal[1] = pal[1];
            dbh[0] = pbh[0]; dbh[1] = pbh[1];
            dbl[0] = pbl[0]; dbl[1] = pbl[1];
        }
        __syncthreads();

        #pragma unroll
        for (int ks = 0; ks < 2; ks++) {
            uint32_t bh[4][2], bl[4][2];
            #pragma unroll
            for (int nt = 0; nt < 4; nt++) {
                const int base = (wn * 32 + nt * 8 + g) * RS + ks * 8 + t;
                bh[nt][0] = wBh[base]; bh[nt][1] = wBh[base + 4];
                bl[nt][0] = wBl[base]; bl[nt][1] = wBl[base + 4];
            }
            #pragma unroll
            for (int mt = 0; mt < 4; mt++) {
                const int base  = (wm * 64 + mt * 16 + g) * RS + ks * 8 + t;
                const int base8 = base + 8 * RS;
                const uint32_t ah0 = wAh[base],     ah1 = wAh[base8];
                const uint32_t ah2 = wAh[base + 4], ah3 = wAh[base8 + 4];
                const uint32_t al0 = wAl[base],     al1 = wAl[base8];
                const uint32_t al2 = wAl[base + 4], al3 = wAl[base8 + 4];
                #pragma unroll
                for (int nt = 0; nt < 4; nt++) {
                    MMA_BF16(acc[mt][nt], ah0, ah1, ah2, ah3, bh[nt][0], bh[nt][1]);
                    MMA_BF16(acc[mt][nt], ah0, ah1, ah2, ah3, bl[nt][0], bl[nt][1]);
                    MMA_BF16(acc[mt][nt], al0, al1, al2, al3, bh[nt][0], bh[nt][1]);
                }
            }
        }
        __syncthreads();
    }

    // epilogue: element (mt, nt, reg): m = m0+wm*64+mt*16+g+(reg>=2)*8,
    //                                  n = n0+wn*32+nt*8+t*2+(reg&1)
    if (MODE == 0 || MODE == 1) {
        #pragma unroll
        for (int mt = 0; mt < 4; mt++) {
            const int mb = m0 + wm * 64 + mt * 16 + g;
            const float bmA = (MODE == 1) ? bias[mb]     : 0.f;
            const float bmB = (MODE == 1) ? bias[mb + 8] : 0.f;
            #pragma unroll
            for (int nt = 0; nt < 4; nt++) {
                const int nb = n0 + wn * 32 + nt * 8 + t * 2;
                float b0, b1;
                if (MODE == 0) { b0 = bias[nb]; b1 = bias[nb + 1]; }
                float2 v0, v1;
                if (MODE == 0) {
                    v0 = make_float2(acc[mt][nt][0] + b0, acc[mt][nt][1] + b1);
                    v1 = make_float2(acc[mt][nt][2] + b0, acc[mt][nt][3] + b1);
                } else {
                    v0 = make_float2(acc[mt][nt][0] + bmA, acc[mt][nt][1] + bmA);
                    v1 = make_float2(acc[mt][nt][2] + bmB, acc[mt][nt][3] + bmB);
                }
                *(float2*)&C[(size_t)mb * ldc + nb]       = v0;
                *(float2*)&C[(size_t)(mb + 8) * ldc + nb] = v1;
            }
        }
    } else { // MODE 2 : up3d scatter
        int nw[4][2], nh[4][2], nd[4][2];
        #pragma unroll
        for (int nt = 0; nt < 4; nt++)
            #pragma unroll
            for (int e = 0; e < 2; e++) {
                const int n = n0 + wn * 32 + nt * 8 + t * 2 + e;
                nw[nt][e] = n % Win;
                const int tt = n / Win;
                nh[nt][e] = tt % Hin;
                nd[nt][e] = tt / Hin;
            }
        const int OD = 2 * Din, OH = 2 * Hin, OW = 2 * Win;
        #pragma unroll
        for (int mt = 0; mt < 4; mt++) {
            #pragma unroll
            for (int half = 0; half < 2; half++) {
                const int m = m0 + wm * 64 + mt * 16 + g + half * 8;
                const int o = m >> 3, r = m & 7;
                const int ri = (r >> 2) & 1, rj = (r >> 1) & 1, rk = r & 1;
                const float bv = bias[o];
                #pragma unroll
                for (int nt = 0; nt < 4; nt++) {
                    #pragma unroll
                    for (int e = 0; e < 2; e++) {
                        float v = acc[mt][nt][half * 2 + e] + bv;
                        if (SILU) v = v / (1.f + __expf(-v));
                        const size_t idx =
                            ((size_t)(o * OD + 2 * nd[nt][e] + ri) * OH
                             + 2 * nh[nt][e] + rj) * OW + 2 * nw[nt][e] + rk;
                        C[idx] = v;
                    }
                }
            }
        }
    }
}

// ---------------------------------------------------------------------------
// Double-buffered fp32 SGEMM (kept for press2 / surf chain)
// ---------------------------------------------------------------------------
template<int BM, bool TA, bool TB, int MODE, bool SILU>
__global__ __launch_bounds__(BM * 2)
void gemm_db(const float* __restrict__ A, const float* __restrict__ B,
             const float* __restrict__ bias, float* __restrict__ C,
             int M, int N, int K, int lda, int ldb, int ldc,
             int Din, int Hin, int Win)
{
    constexpr int THREADS = BM * 2;
    __shared__ float As[2][8][BM];
    __shared__ float Bs[2][8][128];
    const int tid = threadIdx.x;
    const int m0 = blockIdx.y * BM;
    const int n0 = blockIdx.x * 128;
    const int tx = tid & 15, ty = tid >> 4;

    int a_k, a_m;
    if (TA) { a_k = tid / (BM / 4); a_m = (tid % (BM / 4)) * 4; }
    else    { a_m = tid >> 1;       a_k = (tid & 1) << 2; }
    const int bn_k = TB ? ((tid & 1) << 2) : (tid >> 5);
    const int bn_n = TB ? (tid >> 1)       : ((tid & 31) << 2);

    float4 ra, rb0, rb1;

    auto ldA = [&](int k0) {
        if (TA) {
            const float* p = A + (size_t)(k0 + a_k) * lda + m0 + a_m;
            float4 v;
            if (m0 + a_m + 3 < M) v = *(const float4*)p;
            else {
                v.x = (m0 + a_m     < M) ? p[0] : 0.f;
                v.y = (m0 + a_m + 1 < M) ? p[1] : 0.f;
                v.z = (m0 + a_m + 2 < M) ? p[2] : 0.f;
                v.w = (m0 + a_m + 3 < M) ? p[3] : 0.f;
            }
            ra = v;
        } else {
            float4 v = make_float4(0.f, 0.f, 0.f, 0.f);
            if (m0 + a_m < M) v = *(const float4*)(A + (size_t)(m0 + a_m) * lda + k0 + a_k);
            ra = v;
        }
    };
    auto ldB = [&](int k0) {
        if (TB) {
            rb0 = *(const float4*)(B + (size_t)(n0 + bn_n) * ldb + k0 + bn_k);
        } else {
            rb0 = *(const float4*)(B + (size_t)(k0 + bn_k) * ldb + n0 + bn_n);
            if (THREADS == 128)
                rb1 = *(const float4*)(B + (size_t)(k0 + bn_k + 4) * ldb + n0 + bn_n);
        }
    };
    auto stA = [&](int buf) {
        if (TA) {
            *(float4*)&As[buf][a_k][a_m] = ra;
        } else {
            As[buf][a_k + 0][a_m] = ra.x; As[buf][a_k + 1][a_m] = ra.y;
            As[buf][a_k + 2][a_m] = ra.z; As[buf][a_k + 3][a_m] = ra.w;
        }
    };
    auto stB = [&](int buf) {
        if (TB) {
            Bs[buf][bn_k + 0][bn_n] = rb0.x; Bs[buf][bn_k + 1][bn_n] = rb0.y;
            Bs[buf][bn_k + 2][bn_n] = rb0.z; Bs[buf][bn_k + 3][bn_n] = rb0.w;
        } else {
            *(float4*)&Bs[buf][bn_k][bn_n] = rb0;
            if (THREADS == 128) *(float4*)&Bs[buf][bn_k + 4][bn_n] = rb1;
        }
    };

    float acc[8][8] = {};

    ldA(0); ldB(0);
    stA(0); stB(0);
    __syncthreads();

    const int nslab = K >> 3;
    int buf = 0;
    for (int s = 0; s < nslab; s++) {
        if (s + 1 < nslab) { ldA((s + 1) << 3); ldB((s + 1) << 3); }
        #pragma unroll
        for (int kk = 0; kk < 8; kk++) {
            float a[8], b[8];
            *(float4*)&a[0] = *(float4*)&As[buf][kk][ty * 4];
            *(float4*)&a[4] = *(float4*)&As[buf][kk][ty * 4 + BM / 2];
            *(float4*)&b[0] = *(float4*)&Bs[buf][kk][tx * 4];
            *(float4*)&b[4] = *(float4*)&Bs[buf][kk][tx * 4 + 64];
            #pragma unroll
            for (int i = 0; i < 8; i++)
                #pragma unroll
                for (int j = 0; j < 8; j++)
                    acc[i][j] += a[i] * b[j];
        }
        if (s + 1 < nslab) {
            stA(buf ^ 1); stB(buf ^ 1);
            __syncthreads();
            buf ^= 1;
        }
    }

    if (MODE == 0 || MODE == 1) {
        float bn[8];
        if (MODE == 0) {
            *(float4*)&bn[0] = *(const float4*)(bias + n0 + tx * 4);
            *(float4*)&bn[4] = *(const float4*)(bias + n0 + tx * 4 + 64);
        }
        #pragma unroll
        for (int i = 0; i < 8; i++) {
            const int m = m0 + ty * 4 + (i & 3) + ((i >> 2) * (BM / 2));
            if (m < M) {
                const float bm = (MODE == 1) ? bias[m] : 0.f;
                float4 v0, v1;
                v0.x = acc[i][0] + (MODE == 0 ? bn[0] : bm);
                v0.y = acc[i][1] + (MODE == 0 ? bn[1] : bm);
                v0.z = acc[i][2] + (MODE == 0 ? bn[2] : bm);
                v0.w = acc[i][3] + (MODE == 0 ? bn[3] : bm);
                v1.x = acc[i][4] + (MODE == 0 ? bn[4] : bm);
                v1.y = acc[i][5] + (MODE == 0 ? bn[5] : bm);
                v1.z = acc[i][6] + (MODE == 0 ? bn[6] : bm);
                v1.w = acc[i][7] + (MODE == 0 ? bn[7] : bm);
                *(float4*)(C + (size_t)m * ldc + n0 + tx * 4)      = v0;
                *(float4*)(C + (size_t)m * ldc + n0 + tx * 4 + 64) = v1;
            }
        }
    } else if (MODE == 2) {
        int dj[8], hj[8], wj[8];
        #pragma unroll
        for (int j = 0; j < 8; j++) {
            const int n = n0 + tx * 4 + (j & 3) + ((j >> 2) * 64);
            wj[j] = n % Win;
            const int t = n / Win;
            hj[j] = t % Hin;
            dj[j] = t / Hin;
        }
        const int OD = 2 * Din, OH = 2 * Hin, OW = 2 * Win;
        #pragma unroll
        for (int i = 0; i < 8; i++) {
            const int m = m0 + ty * 4 + (i & 3) + ((i >> 2) * (BM / 2));
            if (m < M) {
                const int o = m >> 3, r = m & 7;
                const int ri = (r >> 2) & 1, rj = (r >> 1) & 1, rk = r & 1;
                const float bv = bias[o];
                #pragma unroll
                for (int j = 0; j < 8; j++) {
                    float v = acc[i][j] + bv;
                    if (SILU) v = v / (1.f + __expf(-v));
                    const size_t idx =
                        ((size_t)(o * OD + 2 * dj[j] + ri) * OH + 2 * hj[j] + rj) * OW
                        + 2 * wj[j] + rk;
                    C[idx] = v;
                }
            }
        }
    } else { // MODE 3
        int hj[8], wj[8];
        #pragma unroll
        for (int j = 0; j < 8; j++) {
            const int n = n0 + tx * 4 + (j & 3) + ((j >> 2) * 64);
            wj[j] = n % Win;
            hj[j] = n / Win;
        }
        const int OH = 2 * Hin, OW = 2 * Win;
        #pragma unroll
        for (int i = 0; i < 8; i++) {
            const int m = m0 + ty * 4 + (i & 3) + ((i >> 2) * (BM / 2));
            if (m < M) {
                const int o = m >> 2, r = m & 3;
                const int ri = (r >> 1) & 1, rj = r & 1;
                const float bv = bias[o];
                #pragma unroll
                for (int j = 0; j < 8; j++) {
                    float v = acc[i][j] + bv;
                    if (SILU) v = v / (1.f + __expf(-v));
                    const size_t idx =
                        (size_t)(o * OH + 2 * hj[j] + ri) * OW + 2 * wj[j] + rj;
                    C[idx] = v;
                }
            }
        }
    }
}

// ---------------------------------------------------------------------------
// 3D neighborhood attention v2: 3-phase, shuffle-light.
// Block = token, warp = head.
//  P1: lane owns neighbors {lane, lane+32, lane+64}; private 32-dim dot.
//  P2: one warp max-reduce + one sum-reduce; probs to smem.
//  P3: lane = dim; coalesced V loads, smem-broadcast probs.
// ---------------------------------------------------------------------------
__global__ void na3d_attn_v2(const float* __restrict__ qkv, float* __restrict__ out)
{
    __shared__ float sq[NHEAD][HDIM];
    __shared__ float sp[NHEAD][75];

    const int t = blockIdx.x;
    const int d = t / (HH * WW);
    const int rem = t % (HH * WW);
    const int h = rem / WW;
    const int w = rem % WW;
    const int head = threadIdx.x >> 5;
    const int lane = threadIdx.x & 31;

    const int sd = min(max(d - 1, 0), DD - 3);
    const int sh = min(max(h - 2, 0), HH - 5);
    const int sw = min(max(w - 2, 0), WW - 5);
    const int base = (sd * HH + sh) * WW + sw;

    sq[head][lane] = qkv[t * 768 + head * HDIM + lane] * 0.17677669529663687f;
    __syncwarp();

    // P1: private scores
    float sc[3];
    #pragma unroll
    for (int i = 0; i < 3; i++) {
        const int n = lane + i * 32;
        float s = -1e30f;
        if (n < 75) {
            const int dd = n / 25, r2 = n % 25;
            const int hh2 = r2 / 5, ww2 = r2 % 5;
            const int nb = base + (dd * HH + hh2) * WW + ww2;
            const float4* kr = (const float4*)(qkv + nb * 768 + 256 + head * HDIM);
            const float4* qr = (const float4*)sq[head];
            s = 0.f;
            #pragma unroll
            for (int d4 = 0; d4 < 8; d4++) {
                const float4 k4 = kr[d4], q4 = qr[d4];
                s += q4.x * k4.x + q4.y * k4.y + q4.z * k4.z + q4.w * k4.w;
            }
        }
        sc[i] = s;
    }

    // P2: softmax (one max-reduce, one sum-reduce)
    float m = fmaxf(fmaxf(sc[0], sc[1]), sc[2]);
    #pragma unroll
    for (int o = 16; o; o >>= 1) m = fmaxf(m, __shfl_xor_sync(0xffffffffu, m, o));
    const float e0 = __expf(sc[0] - m);
    const float e1 = __expf(sc[1] - m);
    const float e2 = __expf(sc[2] - m);
    float ssum = e0 + e1 + e2;
    #pragma unroll
    for (int o = 16; o; o >>= 1) ssum += __shfl_xor_sync(0xffffffffu, ssum, o);
    const float inv = 1.f / ssum;
    sp[head][lane] = e0 * inv;
    if (lane + 32 < 75) sp[head][lane + 32] = e1 * inv;
    if (lane + 64 < 75) sp[head][lane + 64] = e2 * inv;
    __syncwarp();

    // P3: PV, lane = dim
    float acc = 0.f;
    const float* vbase = qkv + 512 + head * HDIM + lane;
    int n = 0;
    #pragma unroll
    for (int dd = 0; dd < 3; dd++) {
        #pragma unroll
        for (int hh2 = 0; hh2 < 5; hh2++) {
            const int row = base + (dd * HH + hh2) * WW;
            #pragma unroll
            for (int ww2 = 0; ww2 < 5; ww2++) {
                acc += sp[head][n] * vbase[(size_t)(row + ww2) * 768];
                n++;
            }
        }
    }
    out[t * CH + head * HDIM + lane] = acc;
}

// ---------------------------------------------------------------------------
// Launcher
// ---------------------------------------------------------------------------
extern "C" void kernel_launch(void* const* d_in, const int* in_sizes, int n_in,
                              void* d_out, int out_size)
{
    const float* latent  = (const float*)d_in[0];
    const float* qkv_w   = (const float*)d_in[1];
    const float* qkv_b   = (const float*)d_in[2];
    const float* proj_w  = (const float*)d_in[3];
    const float* proj_b  = (const float*)d_in[4];
    const float* split_w = (const float*)d_in[5];
    const float* split_b = (const float*)d_in[6];
    const float* pw0 = (const float*)d_in[7];
    const float* pb0 = (const float*)d_in[8];
    const float* pw1 = (const float*)d_in[9];
    const float* pb1 = (const float*)d_in[10];
    const float* pw2 = (const float*)d_in[11];
    const float* pb2 = (const float*)d_in[12];
    const float* sw0 = (const float*)d_in[13];
    const float* sb0 = (const float*)d_in[14];
    const float* sw1 = (const float*)d_in[15];
    const float* sb1 = (const float*)d_in[16];
    const float* sw2 = (const float*)d_in[17];
    const float* sb2 = (const float*)d_in[18];
    float* out = (float*)d_out;

    float *qkv, *attn, *x0, *x1, *feats, *p0, *p1, *s0, *s1;
    __nv_bfloat16 *mah, *mal, *mbh, *mbl;
    cudaGetSymbolAddress((void**)&qkv,   g_qkv);
    cudaGetSymbolAddress((void**)&attn,  g_attn);
    cudaGetSymbolAddress((void**)&x0,    g_x0);
    cudaGetSymbolAddress((void**)&x1,    g_x1);
    cudaGetSymbolAddress((void**)&feats, g_feats);
    cudaGetSymbolAddress((void**)&p0,    g_p0);
    cudaGetSymbolAddress((void**)&p1,    g_p1);
    cudaGetSymbolAddress((void**)&s0,    g_s0);
    cudaGetSymbolAddress((void**)&s1,    g_s1);
    cudaGetSymbolAddress((void**)&mah,   g_mah);
    cudaGetSymbolAddress((void**)&mal,   g_mal);
    cudaGetSymbolAddress((void**)&mbh,   g_mbh);
    cudaGetSymbolAddress((void**)&mbl,   g_mbl);

    const dim3 tb(32, 8);
    float* xb[2] = { x0, x1 };
    const float* xin = latent;

    for (int l = 0; l < 3; l++) {
        // qkv: A = xin [5760,256], B = qkv_w [256,768] -> BT [768][256]
        split_rows<<<(TOK * 256 + 255) / 256, 256>>>(xin, mah, mal, TOK * 256);
        transpose_split<<<dim3(768 / 32, 256 / 32), tb>>>(
            qkv_w + l * 256 * 768, mbh, mbl, 256, 768, 768);
        gemm_mma<0, false><<<dim3(768 / 128, TOK / 128), 256>>>(
            mah, mal, mbh, mbl, qkv_b + l * 768, qkv,
            TOK, 768, 256, 768, 0, 0, 0);

        na3d_attn_v2<<<TOK, 256>>>(qkv, attn);

        // proj: A = attn [5760,256], B = proj_w [256,256]
        split_rows<<<(TOK * 256 + 255) / 256, 256>>>(attn, mah, mal, TOK * 256);
        transpose_split<<<dim3(256 / 32, 256 / 32), tb>>>(
            proj_w + l * 256 * 256, mbh, mbl, 256, 256, 256);
        gemm_mma<0, false><<<dim3(256 / 128, TOK / 128), 256>>>(
            mah, mal, mbh, mbl, proj_b + l * 256, xb[l & 1],
            TOK, 256, 256, 256, 0, 0, 0);
        xin = xb[l & 1];
    }

    // split (mma, MODE 1): A = split_w [512][256], B = xin [5760][256]
    split_rows<<<(512 * 256 + 255) / 256, 256>>>(split_w, mah, mal, 512 * 256);
    split_rows<<<(TOK * 256 + 255) / 256, 256>>>(xin, mbh, mbl, TOK * 256);
    gemm_mma<1, false><<<dim3(TOK / 128, 512 / 128), 256>>>(
        mah, mal, mbh, mbl, split_b, feats,
        512, TOK, 256, TOK, 0, 0, 0);

    // press0 (mma): A = pw0T [2048][512], B = featsT [4608][512]
    transpose_split<<<dim3(2048 / 32, 512 / 32), tb>>>(pw0, mah, mal, 512, 2048, 2048);
    transpose_split<<<dim3(4608 / 32, 512 / 32), tb>>>(feats, mbh, mbl, 512, 4608, TOK);
    gemm_mma<2, true><<<dim3(4608 / 128, 2048 / 128), 256>>>(
        mah, mal, mbh, mbl, pb0, p0,
        2048, 4608, 512, 0, 4, 24, 48);

    // press1 (mma): A = pw1T [1024][256], B = p0T [36864][256]
    transpose_split<<<dim3(1024 / 32, 256 / 32), tb>>>(pw1, mah, mal, 256, 1024, 1024);
    transpose_split<<<dim3(36864 / 32, 256 / 32), tb>>>(p0, mbh, mbl, 256, 36864, 36864);
    gemm_mma<2, true><<<dim3(36864 / 128, 1024 / 128), 256>>>(
        mah, mal, mbh, mbl, pb1, p1,
        1024, 36864, 256, 0, 8, 48, 96);

    // press2 (fp32, M=40 -> BM=64)
    gemm_db<64, true, false, 2, false><<<dim3(294912 / 128, 1), 128>>>(
        pw2, p1, pb2, out + 8 * 192 * 384,
        40, 294912, 128, 40, 294912, 0, 16, 96, 192);

    // surf pyramid (fp32 path)
    gemm_db<128, true, false, 3, true><<<dim3(1152 / 128, 1024 / 128), 256>>>(
        sw0, feats + 4 * HH * WW, sb0, s0,
        1024, 1152, 512, 1024, TOK, 0, 0, 24, 48);
    gemm_db<128, true, false, 3, true><<<dim3(4608 / 128, 512 / 128), 256>>>(
        sw1, s0, sb1, s1,
        512, 4608, 256, 512, 4608, 0, 0, 48, 96);
    gemm_db<64, true, false, 3, false><<<dim3(18432 / 128, 1), 128>>>(
        sw2, s1, sb2, out,
        32, 18432, 128, 32, 18432, 0, 0, 96, 192);
}

// round 9
// speedup vs baseline: 1.2007x; 1.2007x over previous
#include <cuda_runtime.h>
#include <cuda_bf16.h>
#include <math.h>
#include <stdint.h>

// ---------------------------------------------------------------------------
// Problem constants
// ---------------------------------------------------------------------------
#define TOK   5760          // 5*24*48
#define CH    256
#define DD    5
#define HH    24
#define WW    48
#define NHEAD 8
#define HDIM  32

// scratch buffers (static device globals; no dynamic allocation allowed)
__device__ float g_qkv [TOK * 768];
__device__ float g_attn[TOK * CH];
__device__ float g_x0  [TOK * CH];
__device__ float g_x1  [TOK * CH];
__device__ float g_feats[512 * TOK];                 // channel-first (512, 5, 24, 48)
__device__ float g_p0  [256 * 8 * 48 * 96];
__device__ float g_p1  [128 * 16 * 96 * 192];
__device__ float g_s0  [256 * 48 * 96];
__device__ float g_s1  [128 * 96 * 192];

// bf16 split scratch (hi/lo), canonical layouts A[M][K], B[N][K]
__device__ __align__(16) __nv_bfloat16 g_mah[1536 * 1024];   // A-side (max 5760*256)
__device__ __align__(16) __nv_bfloat16 g_mal[1536 * 1024];
__device__ __align__(16) __nv_bfloat16 g_mbh[36864 * 256];   // B-side (max p0T)
__device__ __align__(16) __nv_bfloat16 g_mbl[36864 * 256];

// ---------------------------------------------------------------------------
// fp32 -> bf16 hi/lo split, contiguous
// ---------------------------------------------------------------------------
__global__ void split_rows(const float* __restrict__ in,
                           __nv_bfloat16* __restrict__ oh,
                           __nv_bfloat16* __restrict__ ol, int n)
{
    int i = blockIdx.x * blockDim.x + threadIdx.x;
    if (i < n) {
        float v = in[i];
        __nv_bfloat16 h = __float2bfloat16(v);
        oh[i] = h;
        ol[i] = __float2bfloat16(v - __bfloat162float(h));
    }
}

// fp32 [R][C] (row stride ld) -> bf16 hi/lo [C][R]   (R, C multiples of 32)
__global__ void transpose_split(const float* __restrict__ in,
                                __nv_bfloat16* __restrict__ oh,
                                __nv_bfloat16* __restrict__ ol,
                                int R, int C, int ld)
{
    __shared__ float t[32][33];
    const int r0 = blockIdx.y * 32, c0 = blockIdx.x * 32;
    const int tx = threadIdx.x, ty = threadIdx.y;
    #pragma unroll
    for (int i = ty; i < 32; i += 8)
        t[i][tx] = in[(size_t)(r0 + i) * ld + c0 + tx];
    __syncthreads();
    #pragma unroll
    for (int i = ty; i < 32; i += 8) {
        float v = t[tx][i];
        __nv_bfloat16 h = __float2bfloat16(v);
        oh[(size_t)(c0 + i) * R + r0 + tx] = h;
        ol[(size_t)(c0 + i) * R + r0 + tx] = __float2bfloat16(v - __bfloat162float(h));
    }
}

// ---------------------------------------------------------------------------
// Tensor-core GEMM, bf16x3 split (hi*hi + hi*lo + lo*hi), fp32 accum.
//   C[m][n] = epilogue( sum_k A[m][k]*B[k][n] + bias )
// A given as Ah/Al [M][K] bf16, B as Bh/Bl [N][K] bf16.
// Tile 128x128x32, 256 threads = 8 warps (2 m x 4 n), warp tile 64x32,
// mma.sync.m16n8k16. M, N multiples of 128; K multiple of 32.
// MODE 0: C row-major [M][ldc], bias[n]
// MODE 1: C row-major [M][ldc], bias[m]
// MODE 2: up3d scatter, bias[m>>3], optional SiLU
// ---------------------------------------------------------------------------
#define MMA_BF16(c, a0, a1, a2, a3, b0, b1)                                   \
    asm volatile("mma.sync.aligned.m16n8k16.row.col.f32.bf16.bf16.f32 "       \
                 "{%0,%1,%2,%3}, {%4,%5,%6,%7}, {%8,%9}, {%0,%1,%2,%3};"      \
                 : "+f"(c[0]), "+f"(c[1]), "+f"(c[2]), "+f"(c[3])             \
                 : "r"(a0), "r"(a1), "r"(a2), "r"(a3), "r"(b0), "r"(b1))

template<int MODE, bool SILU>
__global__ __launch_bounds__(256)
void gemm_mma(const __nv_bfloat16* __restrict__ Ah, const __nv_bfloat16* __restrict__ Al,
              const __nv_bfloat16* __restrict__ Bh, const __nv_bfloat16* __restrict__ Bl,
              const float* __restrict__ bias, float* __restrict__ C,
              int M, int N, int K, int ldc, int Din, int Hin, int Win)
{
    constexpr int RS = 20;                         // smem words per row (16 data + 4 pad)
    __shared__ float sAh[128 * RS], sAl[128 * RS];
    __shared__ float sBh[128 * RS], sBl[128 * RS];

    const int tid  = threadIdx.x;
    const int warp = tid >> 5, lane = tid & 31;
    const int g = lane >> 2, t = lane & 3;
    const int wm = warp & 1, wn = warp >> 1;       // warp tile origin (wm*64, wn*32)
    const int m0 = blockIdx.y * 128, n0 = blockIdx.x * 128;

    const int lrow = tid >> 1, lseg = tid & 1;     // loader: 2 threads/row, 16 bf16 each

    float acc[4][4][4];
    #pragma unroll
    for (int a = 0; a < 4; a++)
        #pragma unroll
        for (int b = 0; b < 4; b++)
            #pragma unroll
            for (int c = 0; c < 4; c++) acc[a][b][c] = 0.f;

    const uint32_t* wAh = (const uint32_t*)sAh;
    const uint32_t* wAl = (const uint32_t*)sAl;
    const uint32_t* wBh = (const uint32_t*)sBh;
    const uint32_t* wBl = (const uint32_t*)sBl;

    for (int k0 = 0; k0 < K; k0 += 32) {
        {
            const size_t ga = (size_t)(m0 + lrow) * K + k0 + lseg * 16;
            const size_t gb = (size_t)(n0 + lrow) * K + k0 + lseg * 16;
            const uint4* pah = (const uint4*)(Ah + ga);
            const uint4* pal = (const uint4*)(Al + ga);
            const uint4* pbh = (const uint4*)(Bh + gb);
            const uint4* pbl = (const uint4*)(Bl + gb);
            uint4* dah = (uint4*)&sAh[lrow * RS + lseg * 8];
            uint4* dal = (uint4*)&sAl[lrow * RS + lseg * 8];
            uint4* dbh = (uint4*)&sBh[lrow * RS + lseg * 8];
            uint4* dbl = (uint4*)&sBl[lrow * RS + lseg * 8];
            dah[0] = pah[0]; dah[1] = pah[1];
            dal[0] = pal[0]; dal[1] = pal[1];
            dbh[0] = pbh[0]; dbh[1] = pbh[1];
            dbl[0] = pbl[0]; dbl[1] = pbl[1];
        }
        __syncthreads();

        #pragma unroll
        for (int ks = 0; ks < 2; ks++) {
            uint32_t bh[4][2], bl[4][2];
            #pragma unroll
            for (int nt = 0; nt < 4; nt++) {
                const int base = (wn * 32 + nt * 8 + g) * RS + ks * 8 + t;
                bh[nt][0] = wBh[base]; bh[nt][1] = wBh[base + 4];
                bl[nt][0] = wBl[base]; bl[nt][1] = wBl[base + 4];
            }
            #pragma unroll
            for (int mt = 0; mt < 4; mt++) {
                const int base  = (wm * 64 + mt * 16 + g) * RS + ks * 8 + t;
                const int base8 = base + 8 * RS;
                const uint32_t ah0 = wAh[base],     ah1 = wAh[base8];
                const uint32_t ah2 = wAh[base + 4], ah3 = wAh[base8 + 4];
                const uint32_t al0 = wAl[base],     al1 = wAl[base8];
                const uint32_t al2 = wAl[base + 4], al3 = wAl[base8 + 4];
                #pragma unroll
                for (int nt = 0; nt < 4; nt++) {
                    MMA_BF16(acc[mt][nt], ah0, ah1, ah2, ah3, bh[nt][0], bh[nt][1]);
                    MMA_BF16(acc[mt][nt], ah0, ah1, ah2, ah3, bl[nt][0], bl[nt][1]);
                    MMA_BF16(acc[mt][nt], al0, al1, al2, al3, bh[nt][0], bh[nt][1]);
                }
            }
        }
        __syncthreads();
    }

    // epilogue: element (mt, nt, reg): m = m0+wm*64+mt*16+g+(reg>=2)*8,
    //                                  n = n0+wn*32+nt*8+t*2+(reg&1)
    if (MODE == 0 || MODE == 1) {
        #pragma unroll
        for (int mt = 0; mt < 4; mt++) {
            const int mb = m0 + wm * 64 + mt * 16 + g;
            const float bmA = (MODE == 1) ? bias[mb]     : 0.f;
            const float bmB = (MODE == 1) ? bias[mb + 8] : 0.f;
            #pragma unroll
            for (int nt = 0; nt < 4; nt++) {
                const int nb = n0 + wn * 32 + nt * 8 + t * 2;
                float b0, b1;
                if (MODE == 0) { b0 = bias[nb]; b1 = bias[nb + 1]; }
                float2 v0, v1;
                if (MODE == 0) {
                    v0 = make_float2(acc[mt][nt][0] + b0, acc[mt][nt][1] + b1);
                    v1 = make_float2(acc[mt][nt][2] + b0, acc[mt][nt][3] + b1);
                } else {
                    v0 = make_float2(acc[mt][nt][0] + bmA, acc[mt][nt][1] + bmA);
                    v1 = make_float2(acc[mt][nt][2] + bmB, acc[mt][nt][3] + bmB);
                }
                *(float2*)&C[(size_t)mb * ldc + nb]       = v0;
                *(float2*)&C[(size_t)(mb + 8) * ldc + nb] = v1;
            }
        }
    } else { // MODE 2 : up3d scatter
        int nw[4][2], nh[4][2], nd[4][2];
        #pragma unroll
        for (int nt = 0; nt < 4; nt++)
            #pragma unroll
            for (int e = 0; e < 2; e++) {
                const int n = n0 + wn * 32 + nt * 8 + t * 2 + e;
                nw[nt][e] = n % Win;
                const int tt = n / Win;
                nh[nt][e] = tt % Hin;
                nd[nt][e] = tt / Hin;
            }
        const int OD = 2 * Din, OH = 2 * Hin, OW = 2 * Win;
        #pragma unroll
        for (int mt = 0; mt < 4; mt++) {
            #pragma unroll
            for (int half = 0; half < 2; half++) {
                const int m = m0 + wm * 64 + mt * 16 + g + half * 8;
                const int o = m >> 3, r = m & 7;
                const int ri = (r >> 2) & 1, rj = (r >> 1) & 1, rk = r & 1;
                const float bv = bias[o];
                #pragma unroll
                for (int nt = 0; nt < 4; nt++) {
                    #pragma unroll
                    for (int e = 0; e < 2; e++) {
                        float v = acc[mt][nt][half * 2 + e] + bv;
                        if (SILU) v = v / (1.f + __expf(-v));
                        const size_t idx =
                            ((size_t)(o * OD + 2 * nd[nt][e] + ri) * OH
                             + 2 * nh[nt][e] + rj) * OW + 2 * nw[nt][e] + rk;
                        C[idx] = v;
                    }
                }
            }
        }
    }
}

// ---------------------------------------------------------------------------
// Double-buffered fp32 SGEMM (kept for press2 / surf chain)
// ---------------------------------------------------------------------------
template<int BM, bool TA, bool TB, int MODE, bool SILU>
__global__ __launch_bounds__(BM * 2)
void gemm_db(const float* __restrict__ A, const float* __restrict__ B,
             const float* __restrict__ bias, float* __restrict__ C,
             int M, int N, int K, int lda, int ldb, int ldc,
             int Din, int Hin, int Win)
{
    constexpr int THREADS = BM * 2;
    __shared__ float As[2][8][BM];
    __shared__ float Bs[2][8][128];
    const int tid = threadIdx.x;
    const int m0 = blockIdx.y * BM;
    const int n0 = blockIdx.x * 128;
    const int tx = tid & 15, ty = tid >> 4;

    int a_k, a_m;
    if (TA) { a_k = tid / (BM / 4); a_m = (tid % (BM / 4)) * 4; }
    else    { a_m = tid >> 1;       a_k = (tid & 1) << 2; }
    const int bn_k = TB ? ((tid & 1) << 2) : (tid >> 5);
    const int bn_n = TB ? (tid >> 1)       : ((tid & 31) << 2);

    float4 ra, rb0, rb1;

    auto ldA = [&](int k0) {
        if (TA) {
            const float* p = A + (size_t)(k0 + a_k) * lda + m0 + a_m;
            float4 v;
            if (m0 + a_m + 3 < M) v = *(const float4*)p;
            else {
                v.x = (m0 + a_m     < M) ? p[0] : 0.f;
                v.y = (m0 + a_m + 1 < M) ? p[1] : 0.f;
                v.z = (m0 + a_m + 2 < M) ? p[2] : 0.f;
                v.w = (m0 + a_m + 3 < M) ? p[3] : 0.f;
            }
            ra = v;
        } else {
            float4 v = make_float4(0.f, 0.f, 0.f, 0.f);
            if (m0 + a_m < M) v = *(const float4*)(A + (size_t)(m0 + a_m) * lda + k0 + a_k);
            ra = v;
        }
    };
    auto ldB = [&](int k0) {
        if (TB) {
            rb0 = *(const float4*)(B + (size_t)(n0 + bn_n) * ldb + k0 + bn_k);
        } else {
            rb0 = *(const float4*)(B + (size_t)(k0 + bn_k) * ldb + n0 + bn_n);
            if (THREADS == 128)
                rb1 = *(const float4*)(B + (size_t)(k0 + bn_k + 4) * ldb + n0 + bn_n);
        }
    };
    auto stA = [&](int buf) {
        if (TA) {
            *(float4*)&As[buf][a_k][a_m] = ra;
        } else {
            As[buf][a_k + 0][a_m] = ra.x; As[buf][a_k + 1][a_m] = ra.y;
            As[buf][a_k + 2][a_m] = ra.z; As[buf][a_k + 3][a_m] = ra.w;
        }
    };
    auto stB = [&](int buf) {
        if (TB) {
            Bs[buf][bn_k + 0][bn_n] = rb0.x; Bs[buf][bn_k + 1][bn_n] = rb0.y;
            Bs[buf][bn_k + 2][bn_n] = rb0.z; Bs[buf][bn_k + 3][bn_n] = rb0.w;
        } else {
            *(float4*)&Bs[buf][bn_k][bn_n] = rb0;
            if (THREADS == 128) *(float4*)&Bs[buf][bn_k + 4][bn_n] = rb1;
        }
    };

    float acc[8][8] = {};

    ldA(0); ldB(0);
    stA(0); stB(0);
    __syncthreads();

    const int nslab = K >> 3;
    int buf = 0;
    for (int s = 0; s < nslab; s++) {
        if (s + 1 < nslab) { ldA((s + 1) << 3); ldB((s + 1) << 3); }
        #pragma unroll
        for (int kk = 0; kk < 8; kk++) {
            float a[8], b[8];
            *(float4*)&a[0] = *(float4*)&As[buf][kk][ty * 4];
            *(float4*)&a[4] = *(float4*)&As[buf][kk][ty * 4 + BM / 2];
            *(float4*)&b[0] = *(float4*)&Bs[buf][kk][tx * 4];
            *(float4*)&b[4] = *(float4*)&Bs[buf][kk][tx * 4 + 64];
            #pragma unroll
            for (int i = 0; i < 8; i++)
                #pragma unroll
                for (int j = 0; j < 8; j++)
                    acc[i][j] += a[i] * b[j];
        }
        if (s + 1 < nslab) {
            stA(buf ^ 1); stB(buf ^ 1);
            __syncthreads();
            buf ^= 1;
        }
    }

    if (MODE == 0 || MODE == 1) {
        float bn[8];
        if (MODE == 0) {
            *(float4*)&bn[0] = *(const float4*)(bias + n0 + tx * 4);
            *(float4*)&bn[4] = *(const float4*)(bias + n0 + tx * 4 + 64);
        }
        #pragma unroll
        for (int i = 0; i < 8; i++) {
            const int m = m0 + ty * 4 + (i & 3) + ((i >> 2) * (BM / 2));
            if (m < M) {
                const float bm = (MODE == 1) ? bias[m] : 0.f;
                float4 v0, v1;
                v0.x = acc[i][0] + (MODE == 0 ? bn[0] : bm);
                v0.y = acc[i][1] + (MODE == 0 ? bn[1] : bm);
                v0.z = acc[i][2] + (MODE == 0 ? bn[2] : bm);
                v0.w = acc[i][3] + (MODE == 0 ? bn[3] : bm);
                v1.x = acc[i][4] + (MODE == 0 ? bn[4] : bm);
                v1.y = acc[i][5] + (MODE == 0 ? bn[5] : bm);
                v1.z = acc[i][6] + (MODE == 0 ? bn[6] : bm);
                v1.w = acc[i][7] + (MODE == 0 ? bn[7] : bm);
                *(float4*)(C + (size_t)m * ldc + n0 + tx * 4)      = v0;
                *(float4*)(C + (size_t)m * ldc + n0 + tx * 4 + 64) = v1;
            }
        }
    } else if (MODE == 2) {
        int dj[8], hj[8], wj[8];
        #pragma unroll
        for (int j = 0; j < 8; j++) {
            const int n = n0 + tx * 4 + (j & 3) + ((j >> 2) * 64);
            wj[j] = n % Win;
            const int t = n / Win;
            hj[j] = t % Hin;
            dj[j] = t / Hin;
        }
        const int OD = 2 * Din, OH = 2 * Hin, OW = 2 * Win;
        #pragma unroll
        for (int i = 0; i < 8; i++) {
            const int m = m0 + ty * 4 + (i & 3) + ((i >> 2) * (BM / 2));
            if (m < M) {
                const int o = m >> 3, r = m & 7;
                const int ri = (r >> 2) & 1, rj = (r >> 1) & 1, rk = r & 1;
                const float bv = bias[o];
                #pragma unroll
                for (int j = 0; j < 8; j++) {
                    float v = acc[i][j] + bv;
                    if (SILU) v = v / (1.f + __expf(-v));
                    const size_t idx =
                        ((size_t)(o * OD + 2 * dj[j] + ri) * OH + 2 * hj[j] + rj) * OW
                        + 2 * wj[j] + rk;
                    C[idx] = v;
                }
            }
        }
    } else { // MODE 3
        int hj[8], wj[8];
        #pragma unroll
        for (int j = 0; j < 8; j++) {
            const int n = n0 + tx * 4 + (j & 3) + ((j >> 2) * 64);
            wj[j] = n % Win;
            hj[j] = n / Win;
        }
        const int OH = 2 * Hin, OW = 2 * Win;
        #pragma unroll
        for (int i = 0; i < 8; i++) {
            const int m = m0 + ty * 4 + (i & 3) + ((i >> 2) * (BM / 2));
            if (m < M) {
                const int o = m >> 2, r = m & 3;
                const int ri = (r >> 1) & 1, rj = r & 1;
                const float bv = bias[o];
                #pragma unroll
                for (int j = 0; j < 8; j++) {
                    float v = acc[i][j] + bv;
                    if (SILU) v = v / (1.f + __expf(-v));
                    const size_t idx =
                        (size_t)(o * OH + 2 * hj[j] + ri) * OW + 2 * wj[j] + rj;
                    C[idx] = v;
                }
            }
        }
    }
}

// ---------------------------------------------------------------------------
// 3D neighborhood attention v3: quad-parallel scores, coalesced everywhere.
// Block = token, warp = head, quad (4 lanes) = neighbor, lane covers 8 dims.
//  P1: round r: quad qd computes score of neighbor n=r*8+qd.
//      2x float4 coalesced K loads (quad spans the 128B row), 8 FMA,
//      2 intra-quad shuffles. 10 rounds, all independent (ILP).
//  P2: quad-redundant values -> warp max/sum need only offsets 4/8/16.
//  P3: lane = dim; 75 coalesced V loads with smem-broadcast probs.
// ---------------------------------------------------------------------------
__global__ void na3d_attn_v3(const float* __restrict__ qkv, float* __restrict__ out)
{
    __shared__ float sp[NHEAD][80];

    const int t = blockIdx.x;
    const int d = t / (HH * WW);
    const int rem = t % (HH * WW);
    const int h = rem / WW;
    const int w = rem % WW;
    const int head = threadIdx.x >> 5;
    const int lane = threadIdx.x & 31;
    const int qd  = lane >> 2;       // quad id 0..7  -> neighbor slot
    const int sub = lane & 3;        // position in quad -> dim chunk

    const int sd = min(max(d - 1, 0), DD - 3);
    const int sh = min(max(h - 2, 0), HH - 5);
    const int sw = min(max(w - 2, 0), WW - 5);
    const int base = (sd * HH + sh) * WW + sw;

    // q fragment: dims [sub*8, sub*8+8), scaled
    const float* qp = qkv + (size_t)t * 768 + head * HDIM + sub * 8;
    float4 q0 = *(const float4*)qp;
    float4 q1 = *(const float4*)(qp + 4);
    const float sc0 = 0.17677669529663687f;
    q0.x *= sc0; q0.y *= sc0; q0.z *= sc0; q0.w *= sc0;
    q1.x *= sc0; q1.y *= sc0; q1.z *= sc0; q1.w *= sc0;

    // P1: 10 rounds x 8 neighbors
    float sc[10];
    #pragma unroll
    for (int r = 0; r < 10; r++) {
        const int n = r * 8 + qd;
        const int nn = (n < 75) ? n : 74;
        const int dd = nn / 25, r2 = nn % 25;
        const int hh2 = r2 / 5, ww2 = r2 % 5;
        const int nb = base + (dd * HH + hh2) * WW + ww2;
        const float* kp = qkv + (size_t)nb * 768 + 256 + head * HDIM + sub * 8;
        const float4 k0 = *(const float4*)kp;
        const float4 k1 = *(const float4*)(kp + 4);
        float s = q0.x * k0.x + q0.y * k0.y + q0.z * k0.z + q0.w * k0.w
                + q1.x * k1.x + q1.y * k1.y + q1.z * k1.z + q1.w * k1.w;
        s += __shfl_xor_sync(0xffffffffu, s, 1);
        s += __shfl_xor_sync(0xffffffffu, s, 2);
        sc[r] = (n < 75) ? s : -1e30f;
    }

    // P2: softmax (quad-redundant -> reduce across quads only)
    float m = sc[0];
    #pragma unroll
    for (int r = 1; r < 10; r++) m = fmaxf(m, sc[r]);
    m = fmaxf(m, __shfl_xor_sync(0xffffffffu, m, 4));
    m = fmaxf(m, __shfl_xor_sync(0xffffffffu, m, 8));
    m = fmaxf(m, __shfl_xor_sync(0xffffffffu, m, 16));
    float e[10], ssum = 0.f;
    #pragma unroll
    for (int r = 0; r < 10; r++) { e[r] = __expf(sc[r] - m); ssum += e[r]; }
    ssum += __shfl_xor_sync(0xffffffffu, ssum, 4);
    ssum += __shfl_xor_sync(0xffffffffu, ssum, 8);
    ssum += __shfl_xor_sync(0xffffffffu, ssum, 16);
    const float inv = 1.f / ssum;
    if (sub == 0) {
        #pragma unroll
        for (int r = 0; r < 10; r++) {
            const int n = r * 8 + qd;
            if (n < 75) sp[head][n] = e[r] * inv;
        }
    }
    __syncwarp();

    // P3: PV, lane = dim (coalesced)
    float acc = 0.f;
    const float* vbase = qkv + 512 + head * HDIM + lane;
    int n = 0;
    #pragma unroll
    for (int dd = 0; dd < 3; dd++) {
        #pragma unroll
        for (int hh2 = 0; hh2 < 5; hh2++) {
            const int row = base + (dd * HH + hh2) * WW;
            #pragma unroll
            for (int ww2 = 0; ww2 < 5; ww2++) {
                acc += sp[head][n] * vbase[(size_t)(row + ww2) * 768];
                n++;
            }
        }
    }
    out[(size_t)t * CH + head * HDIM + lane] = acc;
}

// ---------------------------------------------------------------------------
// Launcher
// ---------------------------------------------------------------------------
extern "C" void kernel_launch(void* const* d_in, const int* in_sizes, int n_in,
                              void* d_out, int out_size)
{
    const float* latent  = (const float*)d_in[0];
    const float* qkv_w   = (const float*)d_in[1];
    const float* qkv_b   = (const float*)d_in[2];
    const float* proj_w  = (const float*)d_in[3];
    const float* proj_b  = (const float*)d_in[4];
    const float* split_w = (const float*)d_in[5];
    const float* split_b = (const float*)d_in[6];
    const float* pw0 = (const float*)d_in[7];
    const float* pb0 = (const float*)d_in[8];
    const float* pw1 = (const float*)d_in[9];
    const float* pb1 = (const float*)d_in[10];
    const float* pw2 = (const float*)d_in[11];
    const float* pb2 = (const float*)d_in[12];
    const float* sw0 = (const float*)d_in[13];
    const float* sb0 = (const float*)d_in[14];
    const float* sw1 = (const float*)d_in[15];
    const float* sb1 = (const float*)d_in[16];
    const float* sw2 = (const float*)d_in[17];
    const float* sb2 = (const float*)d_in[18];
    float* out = (float*)d_out;

    float *qkv, *attn, *x0, *x1, *feats, *p0, *p1, *s0, *s1;
    __nv_bfloat16 *mah, *mal, *mbh, *mbl;
    cudaGetSymbolAddress((void**)&qkv,   g_qkv);
    cudaGetSymbolAddress((void**)&attn,  g_attn);
    cudaGetSymbolAddress((void**)&x0,    g_x0);
    cudaGetSymbolAddress((void**)&x1,    g_x1);
    cudaGetSymbolAddress((void**)&feats, g_feats);
    cudaGetSymbolAddress((void**)&p0,    g_p0);
    cudaGetSymbolAddress((void**)&p1,    g_p1);
    cudaGetSymbolAddress((void**)&s0,    g_s0);
    cudaGetSymbolAddress((void**)&s1,    g_s1);
    cudaGetSymbolAddress((void**)&mah,   g_mah);
    cudaGetSymbolAddress((void**)&mal,   g_mal);
    cudaGetSymbolAddress((void**)&mbh,   g_mbh);
    cudaGetSymbolAddress((void**)&mbl,   g_mbl);

    const dim3 tb(32, 8);
    float* xb[2] = { x0, x1 };
    const float* xin = latent;

    for (int l = 0; l < 3; l++) {
        // qkv: A = xin [5760,256], B = qkv_w [256,768] -> BT [768][256]
        split_rows<<<(TOK * 256 + 255) / 256, 256>>>(xin, mah, mal, TOK * 256);
        transpose_split<<<dim3(768 / 32, 256 / 32), tb>>>(
            qkv_w + l * 256 * 768, mbh, mbl, 256, 768, 768);
        gemm_mma<0, false><<<dim3(768 / 128, TOK / 128), 256>>>(
            mah, mal, mbh, mbl, qkv_b + l * 768, qkv,
            TOK, 768, 256, 768, 0, 0, 0);

        na3d_attn_v3<<<TOK, 256>>>(qkv, attn);

        // proj: A = attn [5760,256], B = proj_w [256,256]
        split_rows<<<(TOK * 256 + 255) / 256, 256>>>(attn, mah, mal, TOK * 256);
        transpose_split<<<dim3(256 / 32, 256 / 32), tb>>>(
            proj_w + l * 256 * 256, mbh, mbl, 256, 256, 256);
        gemm_mma<0, false><<<dim3(256 / 128, TOK / 128), 256>>>(
            mah, mal, mbh, mbl, proj_b + l * 256, xb[l & 1],
            TOK, 256, 256, 256, 0, 0, 0);
        xin = xb[l & 1];
    }

    // split (mma, MODE 1): A = split_w [512][256], B = xin [5760][256]
    split_rows<<<(512 * 256 + 255) / 256, 256>>>(split_w, mah, mal, 512 * 256);
    split_rows<<<(TOK * 256 + 255) / 256, 256>>>(xin, mbh, mbl, TOK * 256);
    gemm_mma<1, false><<<dim3(TOK / 128, 512 / 128), 256>>>(
        mah, mal, mbh, mbl, split_b, feats,
        512, TOK, 256, TOK, 0, 0, 0);

    // press0 (mma): A = pw0T [2048][512], B = featsT [4608][512]
    transpose_split<<<dim3(2048 / 32, 512 / 32), tb>>>(pw0, mah, mal, 512, 2048, 2048);
    transpose_split<<<dim3(4608 / 32, 512 / 32), tb>>>(feats, mbh, mbl, 512, 4608, TOK);
    gemm_mma<2, true><<<dim3(4608 / 128, 2048 / 128), 256>>>(
        mah, mal, mbh, mbl, pb0, p0,
        2048, 4608, 512, 0, 4, 24, 48);

    // press1 (mma): A = pw1T [1024][256], B = p0T [36864][256]
    transpose_split<<<dim3(1024 / 32, 256 / 32), tb>>>(pw1, mah, mal, 256, 1024, 1024);
    transpose_split<<<dim3(36864 / 32, 256 / 32), tb>>>(p0, mbh, mbl, 256, 36864, 36864);
    gemm_mma<2, true><<<dim3(36864 / 128, 1024 / 128), 256>>>(
        mah, mal, mbh, mbl, pb1, p1,
        1024, 36864, 256, 0, 8, 48, 96);

    // press2 (fp32, M=40 -> BM=64)
    gemm_db<64, true, false, 2, false><<<dim3(294912 / 128, 1), 128>>>(
        pw2, p1, pb2, out + 8 * 192 * 384,
        40, 294912, 128, 40, 294912, 0, 16, 96, 192);

    // surf pyramid (fp32 path)
    gemm_db<128, true, false, 3, true><<<dim3(1152 / 128, 1024 / 128), 256>>>(
        sw0, feats + 4 * HH * WW, sb0, s0,
        1024, 1152, 512, 1024, TOK, 0, 0, 24, 48);
    gemm_db<128, true, false, 3, true><<<dim3(4608 / 128, 512 / 128), 256>>>(
        sw1, s0, sb1, s1,
        512, 4608, 256, 512, 4608, 0, 0, 48, 96);
    gemm_db<64, true, false, 3, false><<<dim3(18432 / 128, 1), 128>>>(
        sw2, s1, sb2, out,
        32, 18432, 128, 32, 18432, 0, 0, 96, 192);
}